// round 13
// baseline (speedup 1.0000x reference)
#include <cuda_runtime.h>
#include <cuda_fp16.h>
#include <math.h>
#include <stdint.h>

#define NTOK 4096
#define DDIM 1024
#define IDIM 4096
#define NEXP 8
#define ROWCAP 9216           // 8192 assignments + 8*128 padding

// ---------------------------------------------------------------------------
// Static scratch
// ---------------------------------------------------------------------------
__device__ int   g_cnt[NEXP];
__device__ int   g_off[NEXP + 1];
__device__ int   g_tok[NEXP * NTOK];
__device__ int   g_prow[NTOK * 2];
__device__ float g_pw[NTOK * 2];

__device__ __half g_xh[(size_t)ROWCAP * DDIM];
__device__ __half g_w1[(size_t)NEXP * IDIM * DDIM];
__device__ __half g_w2[(size_t)NEXP * DDIM * IDIM];
__device__ __half g_h[(size_t)ROWCAP * IDIM];
__device__ float  g_y[(size_t)ROWCAP * DDIM];

// ---------------------------------------------------------------------------
// Helpers (base-target-safe PTX only)
// ---------------------------------------------------------------------------
__device__ __forceinline__ uint32_t smem_u32(const void* p) {
    uint32_t a;
    asm("{ .reg .u64 t; cvta.to.shared.u64 t, %1; cvt.u32.u64 %0, t; }" : "=r"(a) : "l"(p));
    return a;
}
__device__ __forceinline__ uint32_t swz(uint32_t o) { return o ^ ((o >> 3) & 0x70); }

__device__ __forceinline__ void cp16(uint32_t dst, const void* src) {
    asm volatile("cp.async.cg.shared.global [%0], [%1], 16;\n" :: "r"(dst), "l"(src) : "memory");
}
__device__ __forceinline__ void cp_commit() {
    asm volatile("cp.async.commit_group;\n" ::: "memory");
}
template<int N>
__device__ __forceinline__ void cp_wait() {
    asm volatile("cp.async.wait_group %0;\n" :: "n"(N) : "memory");
}
__device__ __forceinline__ void ldm_x4(uint32_t* r, uint32_t addr) {
    asm volatile("ldmatrix.sync.aligned.m8n8.x4.shared.b16 {%0,%1,%2,%3}, [%4];"
                 : "=r"(r[0]), "=r"(r[1]), "=r"(r[2]), "=r"(r[3]) : "r"(addr));
}
__device__ __forceinline__ void mma_f16(float* c, const uint32_t* a, const uint32_t* b) {
    asm volatile(
        "mma.sync.aligned.m16n8k16.row.col.f32.f16.f16.f32 "
        "{%0,%1,%2,%3}, {%4,%5,%6,%7}, {%8,%9}, {%0,%1,%2,%3};"
        : "+f"(c[0]), "+f"(c[1]), "+f"(c[2]), "+f"(c[3])
        : "r"(a[0]), "r"(a[1]), "r"(a[2]), "r"(a[3]), "r"(b[0]), "r"(b[1]));
}
__device__ __forceinline__ uint32_t pack_h2(__half a, __half b) {
    return ((uint32_t)__half_as_ushort(b) << 16) | (uint32_t)__half_as_ushort(a);
}

// ---------------------------------------------------------------------------
// Kernel: zero counters
// ---------------------------------------------------------------------------
__global__ void zero_cnt_kernel() {
    if (threadIdx.x < NEXP) g_cnt[threadIdx.x] = 0;
}

// ---------------------------------------------------------------------------
// Kernel: routing (one block per token)
// ---------------------------------------------------------------------------
__global__ void routing_kernel(const float* __restrict__ x,
                               const float* __restrict__ gw,
                               const float* __restrict__ gb) {
    const int n = blockIdx.x;
    const int tid = threadIdx.x;
    const float* xr = x + (size_t)n * DDIM;

    float acc[NEXP];
#pragma unroll
    for (int e = 0; e < NEXP; e++) acc[e] = 0.f;
    for (int d = tid; d < DDIM; d += 256) {
        const float xv = xr[d];
#pragma unroll
        for (int e = 0; e < NEXP; e++)
            acc[e] = fmaf(xv, gw[e * DDIM + d], acc[e]);
    }
    __shared__ float s[NEXP][256];
#pragma unroll
    for (int e = 0; e < NEXP; e++) s[e][tid] = acc[e];
    __syncthreads();
    for (int off = 128; off > 0; off >>= 1) {
        if (tid < off) {
#pragma unroll
            for (int e = 0; e < NEXP; e++) s[e][tid] += s[e][tid + off];
        }
        __syncthreads();
    }
    if (tid == 0) {
        float logits[NEXP];
#pragma unroll
        for (int e = 0; e < NEXP; e++) logits[e] = s[e][0] + gb[e];
        int i0 = 0; float v0 = logits[0];
#pragma unroll
        for (int e = 1; e < NEXP; e++)
            if (logits[e] > v0) { v0 = logits[e]; i0 = e; }
        int i1 = -1; float v1 = -INFINITY;
#pragma unroll
        for (int e = 0; e < NEXP; e++)
            if (e != i0 && logits[e] > v1) { v1 = logits[e]; i1 = e; }
        const float ew = expf(v1 - v0);
        const float inv = 1.f / (1.f + ew);
        int idx[2] = { i0, i1 };
        float ww[2] = { inv, ew * inv };
#pragma unroll
        for (int k = 0; k < 2; k++) {
            const int e = idx[k];
            const int slot = atomicAdd(&g_cnt[e], 1);
            g_tok[e * NTOK + slot] = n;
            g_prow[n * 2 + k] = e * NTOK + slot;
            g_pw[n * 2 + k] = ww[k];
        }
    }
}

// ---------------------------------------------------------------------------
// Kernel: 128-aligned exclusive prefix of counts
// ---------------------------------------------------------------------------
__global__ void offsets_kernel() {
    if (threadIdx.x == 0) {
        int o = 0;
        for (int e = 0; e < NEXP; e++) {
            g_off[e] = o;
            o += (g_cnt[e] + 127) & ~127;
        }
        g_off[NEXP] = o;
    }
}

// ---------------------------------------------------------------------------
// Kernel: gather token rows -> compacted fp16 layout
// ---------------------------------------------------------------------------
__global__ void gather_x_kernel(const float* __restrict__ x) {
    const int row = blockIdx.x;
    const int tid = threadIdx.x;
    int e = -1, slot = 0;
#pragma unroll
    for (int i = 0; i < NEXP; i++) {
        if (row >= g_off[i] && row < g_off[i + 1]) { e = i; slot = row - g_off[i]; }
    }
    const bool valid = (e >= 0) && (slot < g_cnt[e]);
    uint2* dh = reinterpret_cast<uint2*>(g_xh + (size_t)row * DDIM);
    if (valid) {
        const int token = g_tok[e * NTOK + slot];
        const float4* src = reinterpret_cast<const float4*>(x + (size_t)token * DDIM);
        float4 v = src[tid];
        dh[tid] = make_uint2(pack_h2(__float2half_rn(v.x), __float2half_rn(v.y)),
                             pack_h2(__float2half_rn(v.z), __float2half_rn(v.w)));
    } else {
        dh[tid] = make_uint2(0u, 0u);
    }
}

// ---------------------------------------------------------------------------
// Kernel: weight fp32 -> fp16 (one weight tensor per launch)
// ---------------------------------------------------------------------------
__global__ void convert_w_kernel(const float4* __restrict__ src, int which) {
    __half* dst = which ? g_w2 : g_w1;
    const size_t i = (size_t)blockIdx.x * 256 + threadIdx.x;
    float4 v = src[i];
    reinterpret_cast<uint2*>(dst)[i] =
        make_uint2(pack_h2(__float2half_rn(v.x), __float2half_rn(v.y)),
                   pack_h2(__float2half_rn(v.z), __float2half_rn(v.w)));
}

// ---------------------------------------------------------------------------
// HMMA GEMM: BM=128, BN=128, BK=64, 4 WARPS (2M x 2N), warp tile 64x64.
// fp16 single pass, fp32 acc (128/thread), 2 CTAs/SM.
// SMEM per stage: A 16KB + B 16KB (128 rows x 128B = one SW128 row each).
// 3-stage cp.async ladder, compute-then-prefetch, two syncs per iter
// (round-5/12 discipline; only the stage k-width changed vs round-12).
// ---------------------------------------------------------------------------
#define STAGE_BYTES 32768     // A 16KB + B 16KB
#define NSTAGE 3
#define SMEM_TOTAL  (NSTAGE * STAGE_BYTES)

template<int KDIM, int NCOLS, bool GELU>
__global__ __launch_bounds__(128, 2)
void moe_hmma_kernel(const float* __restrict__ bias) {
    const int e = blockIdx.z;
    const int cnt = g_cnt[e];
    const int m0 = blockIdx.y * 128;
    if (m0 >= cnt) return;
    const int n0 = blockIdx.x * 128;
    const int row0 = g_off[e] + m0;
    const int tid = threadIdx.x;
    const int lane = tid & 31;
    const int wid = tid >> 5;            // 0..3
    const int wm = (wid & 1) * 64;       // warp M offset (2 groups)
    const int wn = (wid >> 1) * 64;      // warp N offset (2 groups)

    const __half* __restrict__ A = GELU ? g_xh : g_h;
    const __half* __restrict__ W = GELU ? g_w1 : g_w2;

    extern __shared__ char smem[];
    const uint32_t sb = smem_u32(smem);

    const size_t wrow0 = (size_t)e * NCOLS + n0;

    // Per stage: A 1024 cp16 + B 1024 cp16 (128 rows x 8 x 16B each);
    // 128 threads -> 8+8 per thread.
    auto load_stage = [&](int s, int k0) {
        const uint32_t st = sb + s * STAGE_BYTES;
#pragma unroll
        for (int i = 0; i < 8; i++) {
            const int idx = tid + i * 128;              // 0..1023
            const int r = idx >> 3;                     // 0..127
            const int c = idx & 7;                      // 16B chunk within 128B
            const uint32_t d = swz(r * 128 + c * 16);
            cp16(st + d, A + (size_t)(row0 + r) * KDIM + k0 + c * 8);
            cp16(st + 16384 + d, W + (wrow0 + r) * KDIM + k0 + c * 8);
        }
        cp_commit();
    };

    float acc[4][8][4];
#pragma unroll
    for (int i = 0; i < 4; i++)
#pragma unroll
        for (int j = 0; j < 8; j++)
#pragma unroll
            for (int q = 0; q < 4; q++) acc[i][j][q] = 0.f;

    constexpr int ITERS = KDIM / 64;
    load_stage(0, 0);
    load_stage(1, 64);
    load_stage(2, 128);

    const int a_row = (lane & 15);
    const int a_kb  = (lane >> 4) * 16;                 // 0 or 16 bytes
    const int b_row = (lane & 7) + ((lane >> 4) * 8);   // 0..15
    const int b_kb  = ((lane >> 3) & 1) * 16;           // 0 or 16 bytes

    for (int it = 0; it < ITERS; it++) {
        if (it <= ITERS - 3)      cp_wait<2>();
        else if (it == ITERS - 2) cp_wait<1>();
        else                      cp_wait<0>();
        __syncthreads();

        const uint32_t Ab = sb + (it % NSTAGE) * STAGE_BYTES;
        const uint32_t Bb = Ab + 16384;

#pragma unroll
        for (int s = 0; s < 4; s++) {
            const int kb = s * 32;                      // bytes within 128B row
            uint32_t af[4][4], bf[8][2];
#pragma unroll
            for (int mt = 0; mt < 4; mt++) {
                const int r = wm + mt * 16 + a_row;
                ldm_x4(af[mt], Ab + swz(r * 128 + kb + a_kb));
            }
#pragma unroll
            for (int p = 0; p < 4; p++) {
                const int r = wn + p * 16 + b_row;
                uint32_t t[4];
                ldm_x4(t, Bb + swz(r * 128 + kb + b_kb));
                bf[2 * p][0] = t[0]; bf[2 * p][1] = t[1];
                bf[2 * p + 1][0] = t[2]; bf[2 * p + 1][1] = t[3];
            }
#pragma unroll
            for (int mt = 0; mt < 4; mt++)
#pragma unroll
                for (int nt = 0; nt < 8; nt++)
                    mma_f16(acc[mt][nt], af[mt], bf[nt]);
        }
        __syncthreads();
        if (it + NSTAGE < ITERS) load_stage(it % NSTAGE, (it + NSTAGE) * 64);
    }

    // ---- epilogue ----
    const float* brow = bias + (size_t)e * NCOLS + n0;
#pragma unroll
    for (int mt = 0; mt < 4; mt++) {
#pragma unroll
        for (int nt = 0; nt < 8; nt++) {
            const int col = wn + nt * 8 + 2 * (lane & 3);
            const float b0 = brow[col], b1 = brow[col + 1];
#pragma unroll
            for (int h = 0; h < 2; h++) {
                const int gr = row0 + wm + mt * 16 + (lane >> 2) + h * 8;
                float v0 = acc[mt][nt][2 * h] + b0;
                float v1 = acc[mt][nt][2 * h + 1] + b1;
                const size_t o = (size_t)gr * NCOLS + n0 + col;
                if (GELU) {
                    v0 = 0.5f * v0 * (1.f + erff(v0 * 0.70710678118654752f));
                    v1 = 0.5f * v1 * (1.f + erff(v1 * 0.70710678118654752f));
                    *reinterpret_cast<uint32_t*>(g_h + o) =
                        pack_h2(__float2half_rn(v0), __float2half_rn(v1));
                } else {
                    *reinterpret_cast<float2*>(g_y + o) = make_float2(v0, v1);
                }
            }
        }
    }
}

// ---------------------------------------------------------------------------
// Kernel: combine. out[n] = w0*y[row0] + w1*y[row1]
// ---------------------------------------------------------------------------
__global__ void combine_kernel(float* __restrict__ out) {
    const int idx = blockIdx.x * 256 + threadIdx.x;
    const int n = idx >> 8;
    const int d = (idx & 255) << 2;
    const int p0 = g_prow[2 * n], p1 = g_prow[2 * n + 1];
    const int r0 = g_off[p0 >> 12] + (p0 & (NTOK - 1));
    const int r1 = g_off[p1 >> 12] + (p1 & (NTOK - 1));
    const float w0 = g_pw[2 * n], w1 = g_pw[2 * n + 1];
    const float4 a = *reinterpret_cast<const float4*>(&g_y[(size_t)r0 * DDIM + d]);
    const float4 b = *reinterpret_cast<const float4*>(&g_y[(size_t)r1 * DDIM + d]);
    float4 o;
    o.x = w0 * a.x + w1 * b.x;
    o.y = w0 * a.y + w1 * b.y;
    o.z = w0 * a.z + w1 * b.z;
    o.w = w0 * a.w + w1 * b.w;
    *reinterpret_cast<float4*>(&out[(size_t)n * DDIM + d]) = o;
}

// ---------------------------------------------------------------------------
// Launch: fork weight conversions onto side streams (round-8 structure)
// ---------------------------------------------------------------------------
extern "C" void kernel_launch(void* const* d_in, const int* in_sizes, int n_in,
                              void* d_out, int out_size) {
    const float* x      = (const float*)d_in[0];
    const float* gate_w = (const float*)d_in[1];
    const float* gate_b = (const float*)d_in[2];
    const float* w1     = (const float*)d_in[3];
    const float* b1     = (const float*)d_in[4];
    const float* w2     = (const float*)d_in[5];
    const float* b2     = (const float*)d_in[6];
    float* out = (float*)d_out;

    static cudaStream_t s1 = nullptr, s2 = nullptr;
    static cudaEvent_t evFork = nullptr, evW1 = nullptr, evW2 = nullptr;
    if (s1 == nullptr) {
        cudaStreamCreateWithFlags(&s1, cudaStreamNonBlocking);
        cudaStreamCreateWithFlags(&s2, cudaStreamNonBlocking);
        cudaEventCreateWithFlags(&evFork, cudaEventDisableTiming);
        cudaEventCreateWithFlags(&evW1, cudaEventDisableTiming);
        cudaEventCreateWithFlags(&evW2, cudaEventDisableTiming);
    }

    cudaFuncSetAttribute(moe_hmma_kernel<DDIM, IDIM, true>,
                         cudaFuncAttributeMaxDynamicSharedMemorySize, SMEM_TOTAL);
    cudaFuncSetAttribute(moe_hmma_kernel<IDIM, DDIM, false>,
                         cudaFuncAttributeMaxDynamicSharedMemorySize, SMEM_TOTAL);

    // fork side streams off the capturing stream
    cudaEventRecord(evFork, 0);
    cudaStreamWaitEvent(s1, evFork, 0);
    cudaStreamWaitEvent(s2, evFork, 0);

    // side stream 1: w1 fp32->fp16
    convert_w_kernel<<<32768, 256, 0, s1>>>((const float4*)w1, 0);
    cudaEventRecord(evW1, s1);
    // side stream 2: w2 fp32->fp16
    convert_w_kernel<<<32768, 256, 0, s2>>>((const float4*)w2, 1);
    cudaEventRecord(evW2, s2);

    // main stream: routing chain
    zero_cnt_kernel<<<1, 32>>>();
    routing_kernel<<<NTOK, 256>>>(x, gate_w, gate_b);
    offsets_kernel<<<1, 1>>>();
    gather_x_kernel<<<ROWCAP, 256>>>(x);

    // GEMM1: h = gelu(xg @ w1^T + b1); K=1024, N=4096
    cudaStreamWaitEvent(0, evW1, 0);
    dim3 g1(IDIM / 128, 32, NEXP);
    moe_hmma_kernel<DDIM, IDIM, true><<<g1, 128, SMEM_TOTAL>>>(b1);

    // GEMM2: y = h @ w2^T + b2; K=4096, N=1024
    cudaStreamWaitEvent(0, evW2, 0);
    dim3 g2(DDIM / 128, 32, NEXP);
    moe_hmma_kernel<IDIM, DDIM, false><<<g2, 128, SMEM_TOTAL>>>(b2);

    combine_kernel<<<(NTOK * DDIM / 4) / 256, 256>>>(out);
}

// round 14
// speedup vs baseline: 1.0319x; 1.0319x over previous
#include <cuda_runtime.h>
#include <cuda_fp16.h>
#include <math.h>
#include <stdint.h>

#define NTOK 4096
#define DDIM 1024
#define IDIM 4096
#define NEXP 8
#define ESLAB 1152            // static rows per expert slab (mean 1024 + 4.3 sigma)
#define ROWCAP (NEXP * ESLAB) // 9216

// ---------------------------------------------------------------------------
// Static scratch
// ---------------------------------------------------------------------------
__device__ int   g_cnt[NEXP];
__device__ int   g_prow[NTOK * 2];          // token -> absolute row (e*ESLAB+slot)
__device__ float g_pw[NTOK * 2];

__device__ __half g_xh[(size_t)ROWCAP * DDIM];
__device__ __half g_w1[(size_t)NEXP * IDIM * DDIM];
__device__ __half g_w2[(size_t)NEXP * DDIM * IDIM];
__device__ __half g_h[(size_t)ROWCAP * IDIM];
__device__ float  g_y[(size_t)ROWCAP * DDIM];

// ---------------------------------------------------------------------------
// Helpers (base-target-safe PTX only)
// ---------------------------------------------------------------------------
__device__ __forceinline__ uint32_t smem_u32(const void* p) {
    uint32_t a;
    asm("{ .reg .u64 t; cvta.to.shared.u64 t, %1; cvt.u32.u64 %0, t; }" : "=r"(a) : "l"(p));
    return a;
}
__device__ __forceinline__ uint32_t swz(uint32_t o) { return o ^ ((o >> 3) & 0x70); }

__device__ __forceinline__ void cp16(uint32_t dst, const void* src) {
    asm volatile("cp.async.cg.shared.global [%0], [%1], 16;\n" :: "r"(dst), "l"(src) : "memory");
}
__device__ __forceinline__ void cp_commit() {
    asm volatile("cp.async.commit_group;\n" ::: "memory");
}
template<int N>
__device__ __forceinline__ void cp_wait() {
    asm volatile("cp.async.wait_group %0;\n" :: "n"(N) : "memory");
}
__device__ __forceinline__ void ldm_x4(uint32_t* r, uint32_t addr) {
    asm volatile("ldmatrix.sync.aligned.m8n8.x4.shared.b16 {%0,%1,%2,%3}, [%4];"
                 : "=r"(r[0]), "=r"(r[1]), "=r"(r[2]), "=r"(r[3]) : "r"(addr));
}
__device__ __forceinline__ void mma_f16(float* c, const uint32_t* a, const uint32_t* b) {
    asm volatile(
        "mma.sync.aligned.m16n8k16.row.col.f32.f16.f16.f32 "
        "{%0,%1,%2,%3}, {%4,%5,%6,%7}, {%8,%9}, {%0,%1,%2,%3};"
        : "+f"(c[0]), "+f"(c[1]), "+f"(c[2]), "+f"(c[3])
        : "r"(a[0]), "r"(a[1]), "r"(a[2]), "r"(a[3]), "r"(b[0]), "r"(b[1]));
}
__device__ __forceinline__ uint32_t pack_h2(__half a, __half b) {
    return ((uint32_t)__half_as_ushort(b) << 16) | (uint32_t)__half_as_ushort(a);
}

// ---------------------------------------------------------------------------
// Kernel: zero counters
// ---------------------------------------------------------------------------
__global__ void zero_cnt_kernel() {
    if (threadIdx.x < NEXP) g_cnt[threadIdx.x] = 0;
}

// ---------------------------------------------------------------------------
// Kernel: fused routing + gather. One WARP per token, 8 tokens per block.
// Computes logits (warp-reduced), top-2 + softmax, claims compacted slots in
// static per-expert slabs, writes the fp16 row into both slabs from registers.
// ---------------------------------------------------------------------------
__global__ __launch_bounds__(256)
void routing_gather_kernel(const float* __restrict__ x,
                           const float* __restrict__ gw,
                           const float* __restrict__ gb) {
    const int warp = threadIdx.x >> 5;
    const int lane = threadIdx.x & 31;
    const int n = blockIdx.x * 8 + warp;

    const float4* xr = reinterpret_cast<const float4*>(x + (size_t)n * DDIM);
    float4 xv[8];
#pragma unroll
    for (int i = 0; i < 8; i++) xv[i] = xr[lane + i * 32];

    float acc[NEXP];
#pragma unroll
    for (int e = 0; e < NEXP; e++) {
        const float4* gwe = reinterpret_cast<const float4*>(gw + e * DDIM);
        float a = 0.f;
#pragma unroll
        for (int i = 0; i < 8; i++) {
            const float4 g = gwe[lane + i * 32];
            a = fmaf(xv[i].x, g.x, a);
            a = fmaf(xv[i].y, g.y, a);
            a = fmaf(xv[i].z, g.z, a);
            a = fmaf(xv[i].w, g.w, a);
        }
        acc[e] = a;
    }
#pragma unroll
    for (int off = 16; off > 0; off >>= 1)
#pragma unroll
        for (int e = 0; e < NEXP; e++)
            acc[e] += __shfl_xor_sync(0xFFFFFFFFu, acc[e], off);

    int row0 = 0, row1 = 0;
    if (lane == 0) {
        float logits[NEXP];
#pragma unroll
        for (int e = 0; e < NEXP; e++) logits[e] = acc[e] + gb[e];
        int i0 = 0; float v0 = logits[0];
#pragma unroll
        for (int e = 1; e < NEXP; e++)
            if (logits[e] > v0) { v0 = logits[e]; i0 = e; }
        int i1 = -1; float v1 = -INFINITY;
#pragma unroll
        for (int e = 0; e < NEXP; e++)
            if (e != i0 && logits[e] > v1) { v1 = logits[e]; i1 = e; }
        const float ew = expf(v1 - v0);
        const float inv = 1.f / (1.f + ew);
        int s0 = atomicAdd(&g_cnt[i0], 1); if (s0 > ESLAB - 1) s0 = ESLAB - 1;
        int s1 = atomicAdd(&g_cnt[i1], 1); if (s1 > ESLAB - 1) s1 = ESLAB - 1;
        row0 = i0 * ESLAB + s0;
        row1 = i1 * ESLAB + s1;
        g_prow[2 * n] = row0;      g_pw[2 * n] = inv;
        g_prow[2 * n + 1] = row1;  g_pw[2 * n + 1] = ew * inv;
    }
    row0 = __shfl_sync(0xFFFFFFFFu, row0, 0);
    row1 = __shfl_sync(0xFFFFFFFFu, row1, 0);

    uint2 ph[8];
#pragma unroll
    for (int i = 0; i < 8; i++)
        ph[i] = make_uint2(pack_h2(__float2half_rn(xv[i].x), __float2half_rn(xv[i].y)),
                           pack_h2(__float2half_rn(xv[i].z), __float2half_rn(xv[i].w)));
    uint2* d0 = reinterpret_cast<uint2*>(g_xh + (size_t)row0 * DDIM);
    uint2* d1 = reinterpret_cast<uint2*>(g_xh + (size_t)row1 * DDIM);
#pragma unroll
    for (int i = 0; i < 8; i++) { d0[lane + i * 32] = ph[i]; d1[lane + i * 32] = ph[i]; }
}

// ---------------------------------------------------------------------------
// Kernel: weight fp32 -> fp16 (one weight tensor per launch)
// ---------------------------------------------------------------------------
__global__ void convert_w_kernel(const float4* __restrict__ src, int which) {
    __half* dst = which ? g_w2 : g_w1;
    const size_t i = (size_t)blockIdx.x * 256 + threadIdx.x;
    float4 v = src[i];
    reinterpret_cast<uint2*>(dst)[i] =
        make_uint2(pack_h2(__float2half_rn(v.x), __float2half_rn(v.y)),
                   pack_h2(__float2half_rn(v.z), __float2half_rn(v.w)));
}

// ---------------------------------------------------------------------------
// HMMA GEMM (round-12 best, byte-identical math; static slab offsets):
// BM=128, BN=128, BK=32, 4 warps (2Mx2N), warp tile 64x64, fp16 single pass,
// fp32 acc, 2 CTAs/SM, 3-stage cp.async ladder, compute-then-prefetch.
// ---------------------------------------------------------------------------
#define STAGE_BYTES 16384     // A 8KB + B 8KB
#define NSTAGE 3
#define SMEM_TOTAL  (NSTAGE * STAGE_BYTES)

template<int KDIM, int NCOLS, bool GELU>
__global__ __launch_bounds__(128, 2)
void moe_hmma_kernel(const float* __restrict__ bias) {
    const int e = blockIdx.z;
    const int cnt = g_cnt[e];
    const int m0 = blockIdx.y * 128;
    if (m0 >= cnt) return;
    const int n0 = blockIdx.x * 128;
    const int row0 = e * ESLAB + m0;
    const int tid = threadIdx.x;
    const int lane = tid & 31;
    const int wid = tid >> 5;            // 0..3
    const int wm = (wid & 1) * 64;       // warp M offset
    const int wn = (wid >> 1) * 64;      // warp N offset

    const __half* __restrict__ A = GELU ? g_xh : g_h;
    const __half* __restrict__ W = GELU ? g_w1 : g_w2;

    extern __shared__ char smem[];
    const uint32_t sb = smem_u32(smem);

    const size_t wrow0 = (size_t)e * NCOLS + n0;

    auto load_stage = [&](int s, int k0) {
        const uint32_t st = sb + s * STAGE_BYTES;
#pragma unroll
        for (int i = 0; i < 4; i++) {
            const int idx = tid + i * 128;              // 0..511
            const int r = idx >> 2;                     // 0..127
            const int c = idx & 3;                      // 16B chunk within 64B
            const uint32_t d = swz((r & 63) * 128 + (r >> 6) * 64 + c * 16);
            cp16(st + d, A + (size_t)(row0 + r) * KDIM + k0 + c * 8);
            cp16(st + 8192 + d, W + (wrow0 + r) * KDIM + k0 + c * 8);
        }
        cp_commit();
    };

    float acc[4][8][4];
#pragma unroll
    for (int i = 0; i < 4; i++)
#pragma unroll
        for (int j = 0; j < 8; j++)
#pragma unroll
            for (int q = 0; q < 4; q++) acc[i][j][q] = 0.f;

    constexpr int ITERS = KDIM / 32;
    load_stage(0, 0);
    load_stage(1, 32);
    load_stage(2, 64);

    const int a_row = (lane & 15);
    const int a_kb  = (lane >> 4) * 16;                 // 0 or 16 bytes
    const int b_row = (lane & 7) + ((lane >> 4) * 8);   // 0..15
    const int b_kb  = ((lane >> 3) & 1) * 16;           // 0 or 16 bytes

    for (int it = 0; it < ITERS; it++) {
        if (it <= ITERS - 3)      cp_wait<2>();
        else if (it == ITERS - 2) cp_wait<1>();
        else                      cp_wait<0>();
        __syncthreads();

        const uint32_t Ab = sb + (it % NSTAGE) * STAGE_BYTES;
        const uint32_t Bb = Ab + 8192;

#pragma unroll
        for (int s = 0; s < 2; s++) {
            const int kb = s * 32;                      // bytes within 64B k-chunk
            uint32_t af[4][4], bf[8][2];
#pragma unroll
            for (int mt = 0; mt < 4; mt++) {
                const int r = wm + mt * 16 + a_row;
                ldm_x4(af[mt], Ab + swz((r & 63) * 128 + (r >> 6) * 64 + kb + a_kb));
            }
#pragma unroll
            for (int p = 0; p < 4; p++) {
                const int nloc = wn + p * 16 + b_row;   // 0..127
                uint32_t t[4];
                ldm_x4(t, Bb + swz((nloc & 63) * 128 + (nloc >> 6) * 64 + kb + b_kb));
                bf[2 * p][0] = t[0]; bf[2 * p][1] = t[1];
                bf[2 * p + 1][0] = t[2]; bf[2 * p + 1][1] = t[3];
            }
#pragma unroll
            for (int mt = 0; mt < 4; mt++)
#pragma unroll
                for (int nt = 0; nt < 8; nt++)
                    mma_f16(acc[mt][nt], af[mt], bf[nt]);
        }
        __syncthreads();
        if (it + NSTAGE < ITERS) load_stage(it % NSTAGE, (it + NSTAGE) * 32);
    }

    // ---- epilogue ----
    const float* brow = bias + (size_t)e * NCOLS + n0;
#pragma unroll
    for (int mt = 0; mt < 4; mt++) {
#pragma unroll
        for (int nt = 0; nt < 8; nt++) {
            const int col = wn + nt * 8 + 2 * (lane & 3);
            const float b0 = brow[col], b1 = brow[col + 1];
#pragma unroll
            for (int h = 0; h < 2; h++) {
                const int gr = row0 + wm + mt * 16 + (lane >> 2) + h * 8;
                float v0 = acc[mt][nt][2 * h] + b0;
                float v1 = acc[mt][nt][2 * h + 1] + b1;
                const size_t o = (size_t)gr * NCOLS + n0 + col;
                if (GELU) {
                    v0 = 0.5f * v0 * (1.f + erff(v0 * 0.70710678118654752f));
                    v1 = 0.5f * v1 * (1.f + erff(v1 * 0.70710678118654752f));
                    *reinterpret_cast<uint32_t*>(g_h + o) =
                        pack_h2(__float2half_rn(v0), __float2half_rn(v1));
                } else {
                    *reinterpret_cast<float2*>(g_y + o) = make_float2(v0, v1);
                }
            }
        }
    }
}

// ---------------------------------------------------------------------------
// Kernel: combine. out[n] = w0*y[row0] + w1*y[row1] (absolute rows)
// ---------------------------------------------------------------------------
__global__ void combine_kernel(float* __restrict__ out) {
    const int idx = blockIdx.x * 256 + threadIdx.x;
    const int n = idx >> 8;
    const int d = (idx & 255) << 2;
    const int r0 = g_prow[2 * n], r1 = g_prow[2 * n + 1];
    const float w0 = g_pw[2 * n], w1 = g_pw[2 * n + 1];
    const float4 a = *reinterpret_cast<const float4*>(&g_y[(size_t)r0 * DDIM + d]);
    const float4 b = *reinterpret_cast<const float4*>(&g_y[(size_t)r1 * DDIM + d]);
    float4 o;
    o.x = w0 * a.x + w1 * b.x;
    o.y = w0 * a.y + w1 * b.y;
    o.z = w0 * a.z + w1 * b.z;
    o.w = w0 * a.w + w1 * b.w;
    *reinterpret_cast<float4*>(&out[(size_t)n * DDIM + d]) = o;
}

// ---------------------------------------------------------------------------
// Launch: fork weight conversions onto side streams (round-8 structure)
// ---------------------------------------------------------------------------
extern "C" void kernel_launch(void* const* d_in, const int* in_sizes, int n_in,
                              void* d_out, int out_size) {
    const float* x      = (const float*)d_in[0];
    const float* gate_w = (const float*)d_in[1];
    const float* gate_b = (const float*)d_in[2];
    const float* w1     = (const float*)d_in[3];
    const float* b1     = (const float*)d_in[4];
    const float* w2     = (const float*)d_in[5];
    const float* b2     = (const float*)d_in[6];
    float* out = (float*)d_out;

    static cudaStream_t s1 = nullptr, s2 = nullptr;
    static cudaEvent_t evFork = nullptr, evW1 = nullptr, evW2 = nullptr;
    if (s1 == nullptr) {
        cudaStreamCreateWithFlags(&s1, cudaStreamNonBlocking);
        cudaStreamCreateWithFlags(&s2, cudaStreamNonBlocking);
        cudaEventCreateWithFlags(&evFork, cudaEventDisableTiming);
        cudaEventCreateWithFlags(&evW1, cudaEventDisableTiming);
        cudaEventCreateWithFlags(&evW2, cudaEventDisableTiming);
    }

    cudaFuncSetAttribute(moe_hmma_kernel<DDIM, IDIM, true>,
                         cudaFuncAttributeMaxDynamicSharedMemorySize, SMEM_TOTAL);
    cudaFuncSetAttribute(moe_hmma_kernel<IDIM, DDIM, false>,
                         cudaFuncAttributeMaxDynamicSharedMemorySize, SMEM_TOTAL);

    // fork side streams off the capturing stream
    cudaEventRecord(evFork, 0);
    cudaStreamWaitEvent(s1, evFork, 0);
    cudaStreamWaitEvent(s2, evFork, 0);

    // side stream 1: w1 fp32->fp16
    convert_w_kernel<<<32768, 256, 0, s1>>>((const float4*)w1, 0);
    cudaEventRecord(evW1, s1);
    // side stream 2: w2 fp32->fp16
    convert_w_kernel<<<32768, 256, 0, s2>>>((const float4*)w2, 1);
    cudaEventRecord(evW2, s2);

    // main stream: fused routing + gather (compacted static slabs)
    zero_cnt_kernel<<<1, 32>>>();
    routing_gather_kernel<<<NTOK / 8, 256>>>(x, gate_w, gate_b);

    // GEMM1: h = gelu(xg @ w1^T + b1); K=1024, N=4096
    cudaStreamWaitEvent(0, evW1, 0);
    dim3 g1(IDIM / 128, ESLAB / 128, NEXP);
    moe_hmma_kernel<DDIM, IDIM, true><<<g1, 128, SMEM_TOTAL>>>(b1);

    // GEMM2: y = h @ w2^T + b2; K=4096, N=1024
    cudaStreamWaitEvent(0, evW2, 0);
    dim3 g2(DDIM / 128, ESLAB / 128, NEXP);
    moe_hmma_kernel<IDIM, DDIM, false><<<g2, 128, SMEM_TOTAL>>>(b2);

    combine_kernel<<<(NTOK * DDIM / 4) / 256, 256>>>(out);
}

// round 15
// speedup vs baseline: 1.0506x; 1.0181x over previous
#include <cuda_runtime.h>
#include <cuda_fp16.h>
#include <math.h>
#include <stdint.h>

#define NTOK 4096
#define DDIM 1024
#define IDIM 4096
#define NEXP 8
#define ESLAB 1152            // static rows per expert slab (mean 1024 + 4.3 sigma)
#define ROWCAP (NEXP * ESLAB) // 9216

// ---------------------------------------------------------------------------
// Static scratch
// ---------------------------------------------------------------------------
__device__ int   g_cnt[NEXP];
__device__ int   g_prow[NTOK * 2];          // token -> absolute row (e*ESLAB+slot)
__device__ float g_pw[NTOK * 2];

__device__ __half g_xh[(size_t)ROWCAP * DDIM];
__device__ __half g_w1[(size_t)NEXP * IDIM * DDIM];
__device__ __half g_w2[(size_t)NEXP * DDIM * IDIM];
__device__ __half g_h[(size_t)ROWCAP * IDIM];
__device__ float  g_y[(size_t)ROWCAP * DDIM];

// ---------------------------------------------------------------------------
// Helpers (base-target-safe PTX only)
// ---------------------------------------------------------------------------
__device__ __forceinline__ uint32_t smem_u32(const void* p) {
    uint32_t a;
    asm("{ .reg .u64 t; cvta.to.shared.u64 t, %1; cvt.u32.u64 %0, t; }" : "=r"(a) : "l"(p));
    return a;
}
__device__ __forceinline__ uint32_t swz(uint32_t o) { return o ^ ((o >> 3) & 0x70); }

__device__ __forceinline__ void cp16(uint32_t dst, const void* src) {
    asm volatile("cp.async.cg.shared.global [%0], [%1], 16;\n" :: "r"(dst), "l"(src) : "memory");
}
__device__ __forceinline__ void cp_commit() {
    asm volatile("cp.async.commit_group;\n" ::: "memory");
}
template<int N>
__device__ __forceinline__ void cp_wait() {
    asm volatile("cp.async.wait_group %0;\n" :: "n"(N) : "memory");
}
__device__ __forceinline__ void ldm_x4(uint32_t* r, uint32_t addr) {
    asm volatile("ldmatrix.sync.aligned.m8n8.x4.shared.b16 {%0,%1,%2,%3}, [%4];"
                 : "=r"(r[0]), "=r"(r[1]), "=r"(r[2]), "=r"(r[3]) : "r"(addr));
}
__device__ __forceinline__ void mma_f16(float* c, const uint32_t* a, const uint32_t* b) {
    asm volatile(
        "mma.sync.aligned.m16n8k16.row.col.f32.f16.f16.f32 "
        "{%0,%1,%2,%3}, {%4,%5,%6,%7}, {%8,%9}, {%0,%1,%2,%3};"
        : "+f"(c[0]), "+f"(c[1]), "+f"(c[2]), "+f"(c[3])
        : "r"(a[0]), "r"(a[1]), "r"(a[2]), "r"(a[3]), "r"(b[0]), "r"(b[1]));
}
__device__ __forceinline__ uint32_t pack_h2(__half a, __half b) {
    return ((uint32_t)__half_as_ushort(b) << 16) | (uint32_t)__half_as_ushort(a);
}

// ---------------------------------------------------------------------------
// Kernel: zero counters
// ---------------------------------------------------------------------------
__global__ void zero_cnt_kernel() {
    if (threadIdx.x < NEXP) g_cnt[threadIdx.x] = 0;
}

// ---------------------------------------------------------------------------
// Kernel: fused routing + gather. One WARP per token, 8 tokens per block.
// ---------------------------------------------------------------------------
__global__ __launch_bounds__(256)
void routing_gather_kernel(const float* __restrict__ x,
                           const float* __restrict__ gw,
                           const float* __restrict__ gb) {
    const int warp = threadIdx.x >> 5;
    const int lane = threadIdx.x & 31;
    const int n = blockIdx.x * 8 + warp;

    const float4* xr = reinterpret_cast<const float4*>(x + (size_t)n * DDIM);
    float4 xv[8];
#pragma unroll
    for (int i = 0; i < 8; i++) xv[i] = xr[lane + i * 32];

    float acc[NEXP];
#pragma unroll
    for (int e = 0; e < NEXP; e++) {
        const float4* gwe = reinterpret_cast<const float4*>(gw + e * DDIM);
        float a = 0.f;
#pragma unroll
        for (int i = 0; i < 8; i++) {
            const float4 g = gwe[lane + i * 32];
            a = fmaf(xv[i].x, g.x, a);
            a = fmaf(xv[i].y, g.y, a);
            a = fmaf(xv[i].z, g.z, a);
            a = fmaf(xv[i].w, g.w, a);
        }
        acc[e] = a;
    }
#pragma unroll
    for (int off = 16; off > 0; off >>= 1)
#pragma unroll
        for (int e = 0; e < NEXP; e++)
            acc[e] += __shfl_xor_sync(0xFFFFFFFFu, acc[e], off);

    int row0 = 0, row1 = 0;
    if (lane == 0) {
        float logits[NEXP];
#pragma unroll
        for (int e = 0; e < NEXP; e++) logits[e] = acc[e] + gb[e];
        int i0 = 0; float v0 = logits[0];
#pragma unroll
        for (int e = 1; e < NEXP; e++)
            if (logits[e] > v0) { v0 = logits[e]; i0 = e; }
        int i1 = -1; float v1 = -INFINITY;
#pragma unroll
        for (int e = 0; e < NEXP; e++)
            if (e != i0 && logits[e] > v1) { v1 = logits[e]; i1 = e; }
        const float ew = expf(v1 - v0);
        const float inv = 1.f / (1.f + ew);
        int s0 = atomicAdd(&g_cnt[i0], 1); if (s0 > ESLAB - 1) s0 = ESLAB - 1;
        int s1 = atomicAdd(&g_cnt[i1], 1); if (s1 > ESLAB - 1) s1 = ESLAB - 1;
        row0 = i0 * ESLAB + s0;
        row1 = i1 * ESLAB + s1;
        g_prow[2 * n] = row0;      g_pw[2 * n] = inv;
        g_prow[2 * n + 1] = row1;  g_pw[2 * n + 1] = ew * inv;
    }
    row0 = __shfl_sync(0xFFFFFFFFu, row0, 0);
    row1 = __shfl_sync(0xFFFFFFFFu, row1, 0);

    uint2 ph[8];
#pragma unroll
    for (int i = 0; i < 8; i++)
        ph[i] = make_uint2(pack_h2(__float2half_rn(xv[i].x), __float2half_rn(xv[i].y)),
                           pack_h2(__float2half_rn(xv[i].z), __float2half_rn(xv[i].w)));
    uint2* d0 = reinterpret_cast<uint2*>(g_xh + (size_t)row0 * DDIM);
    uint2* d1 = reinterpret_cast<uint2*>(g_xh + (size_t)row1 * DDIM);
#pragma unroll
    for (int i = 0; i < 8; i++) { d0[lane + i * 32] = ph[i]; d1[lane + i * 32] = ph[i]; }
}

// ---------------------------------------------------------------------------
// Kernel: weight fp32 -> fp16 (one weight tensor per launch)
// ---------------------------------------------------------------------------
__global__ void convert_w_kernel(const float4* __restrict__ src, int which) {
    __half* dst = which ? g_w2 : g_w1;
    const size_t i = (size_t)blockIdx.x * 256 + threadIdx.x;
    float4 v = src[i];
    reinterpret_cast<uint2*>(dst)[i] =
        make_uint2(pack_h2(__float2half_rn(v.x), __float2half_rn(v.y)),
                   pack_h2(__float2half_rn(v.z), __float2half_rn(v.w)));
}

// ---------------------------------------------------------------------------
// HMMA GEMM (round-12 best, byte-identical; static slab offsets):
// BM=128, BN=128, BK=32, 4 warps (2Mx2N), warp tile 64x64, fp16 single pass,
// fp32 acc, 2 CTAs/SM, 3-stage cp.async ladder, compute-then-prefetch.
// ---------------------------------------------------------------------------
#define STAGE_BYTES 16384     // A 8KB + B 8KB
#define NSTAGE 3
#define SMEM_TOTAL  (NSTAGE * STAGE_BYTES)

template<int KDIM, int NCOLS, bool GELU>
__global__ __launch_bounds__(128, 2)
void moe_hmma_kernel(const float* __restrict__ bias) {
    const int e = blockIdx.z;
    const int cnt = g_cnt[e];
    const int m0 = blockIdx.y * 128;
    if (m0 >= cnt) return;
    const int n0 = blockIdx.x * 128;
    const int row0 = e * ESLAB + m0;
    const int tid = threadIdx.x;
    const int lane = tid & 31;
    const int wid = tid >> 5;            // 0..3
    const int wm = (wid & 1) * 64;       // warp M offset
    const int wn = (wid >> 1) * 64;      // warp N offset

    const __half* __restrict__ A = GELU ? g_xh : g_h;
    const __half* __restrict__ W = GELU ? g_w1 : g_w2;

    extern __shared__ char smem[];
    const uint32_t sb = smem_u32(smem);

    const size_t wrow0 = (size_t)e * NCOLS + n0;

    auto load_stage = [&](int s, int k0) {
        const uint32_t st = sb + s * STAGE_BYTES;
#pragma unroll
        for (int i = 0; i < 4; i++) {
            const int idx = tid + i * 128;              // 0..511
            const int r = idx >> 2;                     // 0..127
            const int c = idx & 3;                      // 16B chunk within 64B
            const uint32_t d = swz((r & 63) * 128 + (r >> 6) * 64 + c * 16);
            cp16(st + d, A + (size_t)(row0 + r) * KDIM + k0 + c * 8);
            cp16(st + 8192 + d, W + (wrow0 + r) * KDIM + k0 + c * 8);
        }
        cp_commit();
    };

    float acc[4][8][4];
#pragma unroll
    for (int i = 0; i < 4; i++)
#pragma unroll
        for (int j = 0; j < 8; j++)
#pragma unroll
            for (int q = 0; q < 4; q++) acc[i][j][q] = 0.f;

    constexpr int ITERS = KDIM / 32;
    load_stage(0, 0);
    load_stage(1, 32);
    load_stage(2, 64);

    const int a_row = (lane & 15);
    const int a_kb  = (lane >> 4) * 16;                 // 0 or 16 bytes
    const int b_row = (lane & 7) + ((lane >> 4) * 8);   // 0..15
    const int b_kb  = ((lane >> 3) & 1) * 16;           // 0 or 16 bytes

    for (int it = 0; it < ITERS; it++) {
        if (it <= ITERS - 3)      cp_wait<2>();
        else if (it == ITERS - 2) cp_wait<1>();
        else                      cp_wait<0>();
        __syncthreads();

        const uint32_t Ab = sb + (it % NSTAGE) * STAGE_BYTES;
        const uint32_t Bb = Ab + 8192;

#pragma unroll
        for (int s = 0; s < 2; s++) {
            const int kb = s * 32;                      // bytes within 64B k-chunk
            uint32_t af[4][4], bf[8][2];
#pragma unroll
            for (int mt = 0; mt < 4; mt++) {
                const int r = wm + mt * 16 + a_row;
                ldm_x4(af[mt], Ab + swz((r & 63) * 128 + (r >> 6) * 64 + kb + a_kb));
            }
#pragma unroll
            for (int p = 0; p < 4; p++) {
                const int nloc = wn + p * 16 + b_row;   // 0..127
                uint32_t t[4];
                ldm_x4(t, Bb + swz((nloc & 63) * 128 + (nloc >> 6) * 64 + kb + b_kb));
                bf[2 * p][0] = t[0]; bf[2 * p][1] = t[1];
                bf[2 * p + 1][0] = t[2]; bf[2 * p + 1][1] = t[3];
            }
#pragma unroll
            for (int mt = 0; mt < 4; mt++)
#pragma unroll
                for (int nt = 0; nt < 8; nt++)
                    mma_f16(acc[mt][nt], af[mt], bf[nt]);
        }
        __syncthreads();
        if (it + NSTAGE < ITERS) load_stage(it % NSTAGE, (it + NSTAGE) * 32);
    }

    // ---- epilogue ----
    const float* brow = bias + (size_t)e * NCOLS + n0;
#pragma unroll
    for (int mt = 0; mt < 4; mt++) {
#pragma unroll
        for (int nt = 0; nt < 8; nt++) {
            const int col = wn + nt * 8 + 2 * (lane & 3);
            const float b0 = brow[col], b1 = brow[col + 1];
#pragma unroll
            for (int h = 0; h < 2; h++) {
                const int gr = row0 + wm + mt * 16 + (lane >> 2) + h * 8;
                float v0 = acc[mt][nt][2 * h] + b0;
                float v1 = acc[mt][nt][2 * h + 1] + b1;
                const size_t o = (size_t)gr * NCOLS + n0 + col;
                if (GELU) {
                    v0 = 0.5f * v0 * (1.f + erff(v0 * 0.70710678118654752f));
                    v1 = 0.5f * v1 * (1.f + erff(v1 * 0.70710678118654752f));
                    *reinterpret_cast<uint32_t*>(g_h + o) =
                        pack_h2(__float2half_rn(v0), __float2half_rn(v1));
                } else {
                    *reinterpret_cast<float2*>(g_y + o) = make_float2(v0, v1);
                }
            }
        }
    }
}

// ---------------------------------------------------------------------------
// Kernel: combine. out[n] = w0*y[row0] + w1*y[row1] (absolute rows)
// ---------------------------------------------------------------------------
__global__ void combine_kernel(float* __restrict__ out) {
    const int idx = blockIdx.x * 256 + threadIdx.x;
    const int n = idx >> 8;
    const int d = (idx & 255) << 2;
    const int r0 = g_prow[2 * n], r1 = g_prow[2 * n + 1];
    const float w0 = g_pw[2 * n], w1 = g_pw[2 * n + 1];
    const float4 a = *reinterpret_cast<const float4*>(&g_y[(size_t)r0 * DDIM + d]);
    const float4 b = *reinterpret_cast<const float4*>(&g_y[(size_t)r1 * DDIM + d]);
    float4 o;
    o.x = w0 * a.x + w1 * b.x;
    o.y = w0 * a.y + w1 * b.y;
    o.z = w0 * a.z + w1 * b.z;
    o.w = w0 * a.w + w1 * b.w;
    *reinterpret_cast<float4*>(&out[(size_t)n * DDIM + d]) = o;
}

// ---------------------------------------------------------------------------
// Launch: w1 convert alone at full BW (gates GEMM1); w2 convert on a LOW-
// PRIORITY stream after w1, backfilling GEMM1's idle slots. Worst case is
// exactly the old schedule; best case hides w2 entirely.
// ---------------------------------------------------------------------------
extern "C" void kernel_launch(void* const* d_in, const int* in_sizes, int n_in,
                              void* d_out, int out_size) {
    const float* x      = (const float*)d_in[0];
    const float* gate_w = (const float*)d_in[1];
    const float* gate_b = (const float*)d_in[2];
    const float* w1     = (const float*)d_in[3];
    const float* b1     = (const float*)d_in[4];
    const float* w2     = (const float*)d_in[5];
    const float* b2     = (const float*)d_in[6];
    float* out = (float*)d_out;

    static cudaStream_t s1 = nullptr, s2 = nullptr;
    static cudaEvent_t evFork = nullptr, evW1 = nullptr, evW2 = nullptr;
    if (s1 == nullptr) {
        int prLeast = 0, prGreatest = 0;
        cudaDeviceGetStreamPriorityRange(&prLeast, &prGreatest);
        cudaStreamCreateWithPriority(&s1, cudaStreamNonBlocking, prGreatest);
        cudaStreamCreateWithPriority(&s2, cudaStreamNonBlocking, prLeast);
        cudaEventCreateWithFlags(&evFork, cudaEventDisableTiming);
        cudaEventCreateWithFlags(&evW1, cudaEventDisableTiming);
        cudaEventCreateWithFlags(&evW2, cudaEventDisableTiming);
    }

    cudaFuncSetAttribute(moe_hmma_kernel<DDIM, IDIM, true>,
                         cudaFuncAttributeMaxDynamicSharedMemorySize, SMEM_TOTAL);
    cudaFuncSetAttribute(moe_hmma_kernel<IDIM, DDIM, false>,
                         cudaFuncAttributeMaxDynamicSharedMemorySize, SMEM_TOTAL);

    // fork side streams off the capturing stream
    cudaEventRecord(evFork, 0);
    cudaStreamWaitEvent(s1, evFork, 0);

    // s1 (high priority): w1 fp32->fp16 alone at full bandwidth
    convert_w_kernel<<<32768, 256, 0, s1>>>((const float4*)w1, 0);
    cudaEventRecord(evW1, s1);

    // s2 (LOW priority): w2 fp32->fp16 after w1 completes; backfills GEMM1
    cudaStreamWaitEvent(s2, evW1, 0);
    convert_w_kernel<<<32768, 256, 0, s2>>>((const float4*)w2, 1);
    cudaEventRecord(evW2, s2);

    // main stream: fused routing + gather (concurrent with w1 convert)
    zero_cnt_kernel<<<1, 32>>>();
    routing_gather_kernel<<<NTOK / 8, 256>>>(x, gate_w, gate_b);

    // GEMM1: h = gelu(xg @ w1^T + b1); K=1024, N=4096
    cudaStreamWaitEvent(0, evW1, 0);
    dim3 g1(IDIM / 128, ESLAB / 128, NEXP);
    moe_hmma_kernel<DDIM, IDIM, true><<<g1, 128, SMEM_TOTAL>>>(b1);

    // GEMM2: y = h @ w2^T + b2; K=4096, N=1024
    cudaStreamWaitEvent(0, evW2, 0);
    dim3 g2(DDIM / 128, ESLAB / 128, NEXP);
    moe_hmma_kernel<IDIM, DDIM, false><<<g2, 128, SMEM_TOTAL>>>(b2);

    combine_kernel<<<(NTOK * DDIM / 4) / 256, 256>>>(out);
}